// round 1
// baseline (speedup 1.0000x reference)
#include <cuda_runtime.h>
#include <math.h>

#define B 1024
#define NNE 100000
#define NRR 500
#define D 200
#define OC 32
#define FW 9
#define LL 192           // D - FW + 1
#define KTOT (OC * LL)   // 6144
#define KFW (OC * FW)    // 288
#define KSPLIT 8
#define EPSV 1e-5f

// scratch (no allocations allowed)
__device__ float g_x[B * D];
__device__ float g_k[B * KFW];
__device__ float g_y[B * KTOT];
__device__ float g_hp[KSPLIT * B * D];
__device__ float g_h[B * D];

// ---------------------------------------------------------------------------
// Kernel A: x = bn0(E[e1_idx]) ; k = R[r_idx] @ W_fc1 + b_fc1
// grid = B, block = 288
// ---------------------------------------------------------------------------
__global__ void kA(const int* __restrict__ e1_idx, const int* __restrict__ r_idx,
                   const float* __restrict__ E, const float* __restrict__ R,
                   const float* __restrict__ W_fc1, const float* __restrict__ b_fc1,
                   const float* __restrict__ g0, const float* __restrict__ b0,
                   const float* __restrict__ m0, const float* __restrict__ v0) {
    int b = blockIdx.x;
    int t = threadIdx.x;
    __shared__ float rs[D];
    const float* Rrow = R + (size_t)r_idx[b] * D;
    if (t < D) {
        rs[t] = Rrow[t];
        float s0 = g0[0] / sqrtf(v0[0] + EPSV);
        g_x[b * D + t] = (E[(size_t)e1_idx[b] * D + t] - m0[0]) * s0 + b0[0];
    }
    __syncthreads();
    float acc = b_fc1[t];
#pragma unroll 4
    for (int d = 0; d < D; d++)
        acc += rs[d] * W_fc1[d * KFW + t];
    g_k[b * KFW + t] = acc;
}

// ---------------------------------------------------------------------------
// Kernel B: y[b,o,l] = sum_w x[b,l+w]*k[b,o,w]; apply bn1; store (B, OC*L)
// grid = B, block = 192 (one thread per l)
// ---------------------------------------------------------------------------
__global__ void kB(const float* __restrict__ g1, const float* __restrict__ b1,
                   const float* __restrict__ m1, const float* __restrict__ v1) {
    int b = blockIdx.x;
    int l = threadIdx.x;
    __shared__ float xs[D];
    __shared__ float ks[KFW];
    for (int i = l; i < D; i += blockDim.x)   xs[i] = g_x[b * D + i];
    for (int i = l; i < KFW; i += blockDim.x) ks[i] = g_k[b * KFW + i];
    __syncthreads();
    float xv[FW];
#pragma unroll
    for (int w = 0; w < FW; w++) xv[w] = xs[l + w];
    for (int o = 0; o < OC; o++) {
        float acc = 0.f;
#pragma unroll
        for (int w = 0; w < FW; w++) acc += xv[w] * ks[o * FW + w];
        float s = g1[o] / sqrtf(v1[o] + EPSV);
        g_y[b * KTOT + o * LL + l] = (acc - m1[o]) * s + b1[o];
    }
}

// ---------------------------------------------------------------------------
// Kernel C1: partial h = Y(1024x6144) @ W_fc(6144x200), split-K
// grid = (32 m-tiles, KSPLIT), block = 200 (one thread per output col d)
// each thread accumulates 32 batch rows over K-chunk of 768
// ---------------------------------------------------------------------------
__global__ void kC1(const float* __restrict__ W_fc) {
    int mt = blockIdx.x;
    int ks = blockIdx.y;
    int d = threadIdx.x;        // 0..199
    int b0 = mt * 32;
    int k0 = ks * (KTOT / KSPLIT);   // 768 chunk
    float acc[32];
#pragma unroll
    for (int i = 0; i < 32; i++) acc[i] = 0.f;
    __shared__ float ys[32][33];
    for (int kc = 0; kc < KTOT / KSPLIT; kc += 32) {
        __syncthreads();
        for (int i = d; i < 32 * 32; i += blockDim.x) {
            int bb = i >> 5, kk = i & 31;
            ys[bb][kk] = g_y[(size_t)(b0 + bb) * KTOT + k0 + kc + kk];
        }
        __syncthreads();
#pragma unroll 4
        for (int kk = 0; kk < 32; kk++) {
            float w = W_fc[(size_t)(k0 + kc + kk) * D + d];
#pragma unroll
            for (int bb = 0; bb < 32; bb++)
                acc[bb] += ys[bb][kk] * w;
        }
    }
    for (int bb = 0; bb < 32; bb++)
        g_hp[(size_t)ks * B * D + (size_t)(b0 + bb) * D + d] = acc[bb];
}

// ---------------------------------------------------------------------------
// Kernel C2: reduce split-K partials, + b_fc, bn2, relu -> g_h
// ---------------------------------------------------------------------------
__global__ void kC2(const float* __restrict__ b_fc,
                    const float* __restrict__ g2, const float* __restrict__ b2,
                    const float* __restrict__ m2, const float* __restrict__ v2) {
    int i = blockIdx.x * blockDim.x + threadIdx.x;
    if (i >= B * D) return;
    int d = i % D;
    float s = 0.f;
#pragma unroll
    for (int ks = 0; ks < KSPLIT; ks++) s += g_hp[(size_t)ks * B * D + i];
    s += b_fc[d];
    float sc = g2[d] / sqrtf(v2[d] + EPSV);
    s = (s - m2[d]) * sc + b2[d];
    g_h[i] = fmaxf(s, 0.f);
}

// ---------------------------------------------------------------------------
// Kernel D: out[b,n] = sigmoid( sum_d h[b,d]*E[n,d] + bias[n] )
// tiled SGEMM: BM=64, BN=64, BK=8; 256 threads; 4x4 per thread
// grid = (ceil(N/64), B/64)
// ---------------------------------------------------------------------------
__global__ void kD(const float* __restrict__ E, const float* __restrict__ bias,
                   float* __restrict__ out) {
    __shared__ __align__(16) float Hs[8][64];
    __shared__ __align__(16) float Es[8][64];
    int n0 = blockIdx.x * 64;
    int m0 = blockIdx.y * 64;
    int tid = threadIdx.x;
    int tx = tid & 15, ty = tid >> 4;
    float acc[4][4] = {};

    for (int k0 = 0; k0 < D; k0 += 8) {
        for (int i = tid; i < 512; i += 256) {
            int m = i >> 3, k = i & 7;
            Hs[k][m] = g_h[(size_t)(m0 + m) * D + k0 + k];
            int gn = n0 + m;
            Es[k][m] = (gn < NNE) ? E[(size_t)gn * D + k0 + k] : 0.f;
        }
        __syncthreads();
#pragma unroll
        for (int kk = 0; kk < 8; kk++) {
            float4 a = ((const float4*)Hs[kk])[ty];
            float4 e = ((const float4*)Es[kk])[tx];
            float av[4] = {a.x, a.y, a.z, a.w};
            float ev[4] = {e.x, e.y, e.z, e.w};
#pragma unroll
            for (int i = 0; i < 4; i++)
#pragma unroll
                for (int j = 0; j < 4; j++)
                    acc[i][j] += av[i] * ev[j];
        }
        __syncthreads();
    }

    int mbase = m0 + ty * 4;
    int nbase = n0 + tx * 4;
#pragma unroll
    for (int i = 0; i < 4; i++) {
#pragma unroll
        for (int j = 0; j < 4; j++) {
            int n = nbase + j;
            if (n < NNE) {
                float v = acc[i][j] + bias[n];
                out[(size_t)(mbase + i) * NNE + n] = 1.f / (1.f + expf(-v));
            }
        }
    }
}

// ---------------------------------------------------------------------------
extern "C" void kernel_launch(void* const* d_in, const int* in_sizes, int n_in,
                              void* d_out, int out_size) {
    const int*   e1_idx = (const int*)d_in[0];
    const int*   r_idx  = (const int*)d_in[1];
    const float* E      = (const float*)d_in[2];
    const float* R      = (const float*)d_in[3];
    const float* W_fc   = (const float*)d_in[4];
    const float* b_fc   = (const float*)d_in[5];
    const float* W_fc1  = (const float*)d_in[6];
    const float* b_fc1  = (const float*)d_in[7];
    const float* bn0_g  = (const float*)d_in[8];
    const float* bn0_b  = (const float*)d_in[9];
    const float* bn0_m  = (const float*)d_in[10];
    const float* bn0_v  = (const float*)d_in[11];
    const float* bn1_g  = (const float*)d_in[12];
    const float* bn1_b  = (const float*)d_in[13];
    const float* bn1_m  = (const float*)d_in[14];
    const float* bn1_v  = (const float*)d_in[15];
    const float* bn2_g  = (const float*)d_in[16];
    const float* bn2_b  = (const float*)d_in[17];
    const float* bn2_m  = (const float*)d_in[18];
    const float* bn2_v  = (const float*)d_in[19];
    const float* bvec   = (const float*)d_in[20];
    float* out = (float*)d_out;

    kA<<<B, KFW>>>(e1_idx, r_idx, E, R, W_fc1, b_fc1, bn0_g, bn0_b, bn0_m, bn0_v);
    kB<<<B, LL>>>(bn1_g, bn1_b, bn1_m, bn1_v);
    kC1<<<dim3(B / 32, KSPLIT), D>>>(W_fc);
    kC2<<<(B * D + 255) / 256, 256>>>(b_fc, bn2_g, bn2_b, bn2_m, bn2_v);
    dim3 gD((NNE + 63) / 64, B / 64);
    kD<<<gD, 256>>>(E, bvec, out);
}

// round 3
// speedup vs baseline: 2.8505x; 2.8505x over previous
#include <cuda_runtime.h>
#include <cuda_bf16.h>
#include <cstdint>
#include <math.h>

#define B 1024
#define NNE 100000
#define NPAD 100096          // padded rows of E (multiple of 128)
#define D 200
#define KP 208               // K padded to multiple of 16
#define OC 32
#define FW 9
#define LL 192               // D - FW + 1
#define KTOT (OC * LL)       // 6144
#define KFW (OC * FW)        // 288
#define KSPLIT 8
#define EPSV 1e-5f

#define BM 64
#define BN 128
#define NKSTEP 13            // KP / 16

// scratch (no allocations allowed)
__device__ float g_x[B * D];
__device__ float g_k[B * KFW];
__device__ float g_y[B * KTOT];
__device__ float g_hp[KSPLIT * B * D];
__device__ __nv_bfloat16 g_hb[B * KP];
__device__ __nv_bfloat16 g_Eb[(size_t)NPAD * KP];

// ---------------------------------------------------------------------------
// Kernel A: x = bn0(E[e1_idx]) ; k = R[r_idx] @ W_fc1 + b_fc1
// ---------------------------------------------------------------------------
__global__ void kA(const int* __restrict__ e1_idx, const int* __restrict__ r_idx,
                   const float* __restrict__ E, const float* __restrict__ R,
                   const float* __restrict__ W_fc1, const float* __restrict__ b_fc1,
                   const float* __restrict__ g0, const float* __restrict__ b0,
                   const float* __restrict__ m0, const float* __restrict__ v0) {
    int b = blockIdx.x;
    int t = threadIdx.x;
    __shared__ float rs[D];
    const float* Rrow = R + (size_t)r_idx[b] * D;
    if (t < D) {
        rs[t] = Rrow[t];
        float s0 = g0[0] / sqrtf(v0[0] + EPSV);
        g_x[b * D + t] = (E[(size_t)e1_idx[b] * D + t] - m0[0]) * s0 + b0[0];
    }
    __syncthreads();
    float acc = b_fc1[t];
#pragma unroll 4
    for (int d = 0; d < D; d++)
        acc += rs[d] * W_fc1[d * KFW + t];
    g_k[b * KFW + t] = acc;
}

// ---------------------------------------------------------------------------
// Kernel B: y[b,o,l] = sum_w x[b,l+w]*k[b,o,w]; bn1
// ---------------------------------------------------------------------------
__global__ void kB(const float* __restrict__ g1, const float* __restrict__ b1,
                   const float* __restrict__ m1, const float* __restrict__ v1) {
    int b = blockIdx.x;
    int l = threadIdx.x;
    __shared__ float xs[D];
    __shared__ float ks[KFW];
    for (int i = l; i < D; i += blockDim.x)   xs[i] = g_x[b * D + i];
    for (int i = l; i < KFW; i += blockDim.x) ks[i] = g_k[b * KFW + i];
    __syncthreads();
    float xv[FW];
#pragma unroll
    for (int w = 0; w < FW; w++) xv[w] = xs[l + w];
    for (int o = 0; o < OC; o++) {
        float acc = 0.f;
#pragma unroll
        for (int w = 0; w < FW; w++) acc += xv[w] * ks[o * FW + w];
        float s = g1[o] / sqrtf(v1[o] + EPSV);
        g_y[b * KTOT + o * LL + l] = (acc - m1[o]) * s + b1[o];
    }
}

// ---------------------------------------------------------------------------
// Kernel C1: partial h = Y(1024x6144) @ W_fc(6144x200), split-K
// ---------------------------------------------------------------------------
__global__ void kC1(const float* __restrict__ W_fc) {
    int mt = blockIdx.x;
    int ks = blockIdx.y;
    int d = threadIdx.x;
    int b0 = mt * 32;
    int k0 = ks * (KTOT / KSPLIT);
    float acc[32];
#pragma unroll
    for (int i = 0; i < 32; i++) acc[i] = 0.f;
    __shared__ float ys[32][33];
    for (int kc = 0; kc < KTOT / KSPLIT; kc += 32) {
        __syncthreads();
        for (int i = d; i < 32 * 32; i += blockDim.x) {
            int bb = i >> 5, kk = i & 31;
            ys[bb][kk] = g_y[(size_t)(b0 + bb) * KTOT + k0 + kc + kk];
        }
        __syncthreads();
#pragma unroll 4
        for (int kk = 0; kk < 32; kk++) {
            float w = W_fc[(size_t)(k0 + kc + kk) * D + d];
#pragma unroll
            for (int bb = 0; bb < 32; bb++)
                acc[bb] += ys[bb][kk] * w;
        }
    }
    for (int bb = 0; bb < 32; bb++)
        g_hp[(size_t)ks * B * D + (size_t)(b0 + bb) * D + d] = acc[bb];
}

// ---------------------------------------------------------------------------
// Kernel C2: reduce split-K, + b_fc, bn2, relu -> g_hb (bf16, K padded)
// ---------------------------------------------------------------------------
__global__ void kC2(const float* __restrict__ b_fc,
                    const float* __restrict__ g2, const float* __restrict__ b2,
                    const float* __restrict__ m2, const float* __restrict__ v2) {
    int i = blockIdx.x * blockDim.x + threadIdx.x;
    if (i >= B * D) return;
    int b = i / D;
    int d = i % D;
    float s = 0.f;
#pragma unroll
    for (int ks = 0; ks < KSPLIT; ks++) s += g_hp[(size_t)ks * B * D + i];
    s += b_fc[d];
    float sc = g2[d] / sqrtf(v2[d] + EPSV);
    s = (s - m2[d]) * sc + b2[d];
    s = fmaxf(s, 0.f);
    g_hb[b * KP + d] = __float2bfloat16(s);
    if (d < KP - D) g_hb[b * KP + D + d] = __float2bfloat16(0.f);
}

// ---------------------------------------------------------------------------
// convE: E (fp32, NNE x D) -> g_Eb (bf16, NPAD x KP) zero-padded
// ---------------------------------------------------------------------------
__global__ void convE(const float* __restrict__ E) {
    size_t i = (size_t)blockIdx.x * blockDim.x + threadIdx.x;
    if (i >= (size_t)NPAD * KP) return;
    int n = (int)(i / KP);
    int k = (int)(i % KP);
    float v = (n < NNE && k < D) ? E[(size_t)n * D + k] : 0.f;
    g_Eb[i] = __float2bfloat16(v);
}

// ---------------------------------------------------------------------------
// Kernel D: out[m,n] = sigmoid( h[m,:] . E[n,:] + bias[n] )
// BF16 mma.sync m16n8k16, BM=64 x BN=128, 256 thr (2x4 warps, 32x32/warp)
// cp.async double-buffered K stages of 16.
// grid = (B/BM, NPAD/BN)
// ---------------------------------------------------------------------------
__global__ void kD(const float* __restrict__ bias, float* __restrict__ out) {
    __shared__ __align__(16) __nv_bfloat16 As[2][BM][24];
    __shared__ __align__(16) __nv_bfloat16 Bs[2][BN][24];

    const int m0 = blockIdx.x * BM;
    const int n0 = blockIdx.y * BN;
    const int tid = threadIdx.x;
    const int lane = tid & 31;
    const int wid = tid >> 5;
    const int wm = wid >> 2;    // 0..1
    const int wn = wid & 3;     // 0..3

    float acc[2][4][4];
#pragma unroll
    for (int i = 0; i < 2; i++)
#pragma unroll
        for (int j = 0; j < 4; j++)
#pragma unroll
            for (int c = 0; c < 4; c++) acc[i][j][c] = 0.f;

    const int arow = tid >> 1, ac8 = (tid & 1) * 8;

#define LOAD_STAGE(S, KS)                                                        \
    do {                                                                         \
        if (tid < 128) {                                                         \
            unsigned dst = (unsigned)__cvta_generic_to_shared(&As[S][arow][ac8]);\
            const __nv_bfloat16* src = &g_hb[(size_t)(m0 + arow) * KP + (KS) + ac8];\
            asm volatile("cp.async.cg.shared.global [%0], [%1], 16;\n"           \
                         :: "r"(dst), "l"(src));                                 \
        }                                                                        \
        {                                                                        \
            unsigned dst = (unsigned)__cvta_generic_to_shared(&Bs[S][arow][ac8]);\
            const __nv_bfloat16* src = &g_Eb[(size_t)(n0 + arow) * KP + (KS) + ac8];\
            asm volatile("cp.async.cg.shared.global [%0], [%1], 16;\n"           \
                         :: "r"(dst), "l"(src));                                 \
        }                                                                        \
        asm volatile("cp.async.commit_group;\n" ::);                             \
    } while (0)

    LOAD_STAGE(0, 0);

    for (int s = 0; s < NKSTEP; s++) {
        if (s + 1 < NKSTEP) {
            LOAD_STAGE((s + 1) & 1, (s + 1) * 16);
            asm volatile("cp.async.wait_group 1;\n" ::);
        } else {
            asm volatile("cp.async.wait_group 0;\n" ::);
        }
        __syncthreads();

        const int st = s & 1;
        unsigned a[2][4];
        unsigned bfr[4][2];

#pragma unroll
        for (int mi = 0; mi < 2; mi++) {
            unsigned addr = (unsigned)__cvta_generic_to_shared(
                &As[st][wm * 32 + mi * 16 + (lane & 15)][(lane >> 4) * 8]);
            asm volatile("ldmatrix.sync.aligned.m8n8.x4.shared.b16 {%0,%1,%2,%3}, [%4];"
                         : "=r"(a[mi][0]), "=r"(a[mi][1]), "=r"(a[mi][2]), "=r"(a[mi][3])
                         : "r"(addr));
        }
#pragma unroll
        for (int p = 0; p < 2; p++) {
            unsigned addr = (unsigned)__cvta_generic_to_shared(
                &Bs[st][wn * 32 + p * 16 + ((lane >> 4) << 3) + (lane & 7)]
                   [((lane >> 3) & 1) * 8]);
            asm volatile("ldmatrix.sync.aligned.m8n8.x4.shared.b16 {%0,%1,%2,%3}, [%4];"
                         : "=r"(bfr[2 * p][0]), "=r"(bfr[2 * p][1]),
                           "=r"(bfr[2 * p + 1][0]), "=r"(bfr[2 * p + 1][1])
                         : "r"(addr));
        }

#pragma unroll
        for (int mi = 0; mi < 2; mi++)
#pragma unroll
            for (int ni = 0; ni < 4; ni++) {
                asm volatile(
                    "mma.sync.aligned.m16n8k16.row.col.f32.bf16.bf16.f32 "
                    "{%0,%1,%2,%3}, {%4,%5,%6,%7}, {%8,%9}, {%0,%1,%2,%3};"
                    : "+f"(acc[mi][ni][0]), "+f"(acc[mi][ni][1]),
                      "+f"(acc[mi][ni][2]), "+f"(acc[mi][ni][3])
                    : "r"(a[mi][0]), "r"(a[mi][1]), "r"(a[mi][2]), "r"(a[mi][3]),
                      "r"(bfr[ni][0]), "r"(bfr[ni][1]));
            }
        __syncthreads();
    }

    // epilogue: bias + sigmoid, guarded stores
    const int rin = lane >> 2;
    const int cin = (lane & 3) * 2;
#pragma unroll
    for (int mi = 0; mi < 2; mi++) {
#pragma unroll
        for (int ni = 0; ni < 4; ni++) {
            int m = m0 + wm * 32 + mi * 16 + rin;
            int n = n0 + wn * 32 + ni * 8 + cin;
            if (n < NNE) {
                float bz = bias[n];
                float v0 = acc[mi][ni][0] + bz;
                float v2 = acc[mi][ni][2] + bz;
                out[(size_t)m * NNE + n]       = 1.f / (1.f + __expf(-v0));
                out[(size_t)(m + 8) * NNE + n] = 1.f / (1.f + __expf(-v2));
            }
            if (n + 1 < NNE) {
                float bz = bias[n + 1];
                float v1 = acc[mi][ni][1] + bz;
                float v3 = acc[mi][ni][3] + bz;
                out[(size_t)m * NNE + n + 1]       = 1.f / (1.f + __expf(-v1));
                out[(size_t)(m + 8) * NNE + n + 1] = 1.f / (1.f + __expf(-v3));
            }
        }
    }
#undef LOAD_STAGE
}

// ---------------------------------------------------------------------------
extern "C" void kernel_launch(void* const* d_in, const int* in_sizes, int n_in,
                              void* d_out, int out_size) {
    const int*   e1_idx = (const int*)d_in[0];
    const int*   r_idx  = (const int*)d_in[1];
    const float* E      = (const float*)d_in[2];
    const float* R      = (const float*)d_in[3];
    const float* W_fc   = (const float*)d_in[4];
    const float* b_fc   = (const float*)d_in[5];
    const float* W_fc1  = (const float*)d_in[6];
    const float* b_fc1  = (const float*)d_in[7];
    const float* bn0_g  = (const float*)d_in[8];
    const float* bn0_b  = (const float*)d_in[9];
    const float* bn0_m  = (const float*)d_in[10];
    const float* bn0_v  = (const float*)d_in[11];
    const float* bn1_g  = (const float*)d_in[12];
    const float* bn1_b  = (const float*)d_in[13];
    const float* bn1_m  = (const float*)d_in[14];
    const float* bn1_v  = (const float*)d_in[15];
    const float* bn2_g  = (const float*)d_in[16];
    const float* bn2_b  = (const float*)d_in[17];
    const float* bn2_m  = (const float*)d_in[18];
    const float* bn2_v  = (const float*)d_in[19];
    const float* bvec   = (const float*)d_in[20];
    float* out = (float*)d_out;

    kA<<<B, KFW>>>(e1_idx, r_idx, E, R, W_fc1, b_fc1, bn0_g, bn0_b, bn0_m, bn0_v);
    kB<<<B, LL>>>(bn1_g, bn1_b, bn1_m, bn1_v);
    kC1<<<dim3(B / 32, KSPLIT), D>>>(W_fc);
    kC2<<<(B * D + 255) / 256, 256>>>(b_fc, bn2_g, bn2_b, bn2_m, bn2_v);

    convE<<<(int)(((size_t)NPAD * KP + 255) / 256), 256>>>(E);

    dim3 gD(B / BM, NPAD / BN);
    kD<<<gD, 256>>>(bvec, out);
}

// round 4
// speedup vs baseline: 3.1368x; 1.1004x over previous
#include <cuda_runtime.h>
#include <cuda_bf16.h>
#include <cstdint>
#include <math.h>

#define B 1024
#define NNE 100000
#define NPAD 100096          // padded rows of E (multiple of 256)
#define D 200
#define KP 208               // K padded to multiple of 16
#define OC 32
#define FW 9
#define LL 192               // D - FW + 1
#define KTOT (OC * LL)       // 6144
#define KFW (OC * FW)        // 288
#define KSPLIT 8
#define EPSV 1e-5f

#define BM 64
#define BN 256
#define NKSTEP 13            // KP / 16
#define NSTG 3               // cp.async stages

// scratch (no allocations allowed)
__device__ float g_x[B * D];
__device__ float g_k[B * KFW];
__device__ float g_y[B * KTOT];
__device__ float g_hp[KSPLIT * B * D];
__device__ __nv_bfloat16 g_hb[B * KP];
__device__ __nv_bfloat16 g_Eb[(size_t)NPAD * KP];

// ---------------------------------------------------------------------------
// Kernel A: x = bn0(E[e1_idx]) ; k = R[r_idx] @ W_fc1 + b_fc1
// ---------------------------------------------------------------------------
__global__ void kA(const int* __restrict__ e1_idx, const int* __restrict__ r_idx,
                   const float* __restrict__ E, const float* __restrict__ R,
                   const float* __restrict__ W_fc1, const float* __restrict__ b_fc1,
                   const float* __restrict__ g0, const float* __restrict__ b0,
                   const float* __restrict__ m0, const float* __restrict__ v0) {
    int b = blockIdx.x;
    int t = threadIdx.x;
    __shared__ float rs[D];
    const float* Rrow = R + (size_t)r_idx[b] * D;
    if (t < D) {
        rs[t] = Rrow[t];
        float s0 = g0[0] / sqrtf(v0[0] + EPSV);
        g_x[b * D + t] = (E[(size_t)e1_idx[b] * D + t] - m0[0]) * s0 + b0[0];
    }
    __syncthreads();
    float acc = b_fc1[t];
#pragma unroll 4
    for (int d = 0; d < D; d++)
        acc += rs[d] * W_fc1[d * KFW + t];
    g_k[b * KFW + t] = acc;
}

// ---------------------------------------------------------------------------
// Kernel B: y[b,o,l] = sum_w x[b,l+w]*k[b,o,w]; bn1
// ---------------------------------------------------------------------------
__global__ void kB(const float* __restrict__ g1, const float* __restrict__ b1,
                   const float* __restrict__ m1, const float* __restrict__ v1) {
    int b = blockIdx.x;
    int l = threadIdx.x;
    __shared__ float xs[D];
    __shared__ float ks[KFW];
    for (int i = l; i < D; i += blockDim.x)   xs[i] = g_x[b * D + i];
    for (int i = l; i < KFW; i += blockDim.x) ks[i] = g_k[b * KFW + i];
    __syncthreads();
    float xv[FW];
#pragma unroll
    for (int w = 0; w < FW; w++) xv[w] = xs[l + w];
    for (int o = 0; o < OC; o++) {
        float acc = 0.f;
#pragma unroll
        for (int w = 0; w < FW; w++) acc += xv[w] * ks[o * FW + w];
        float s = g1[o] / sqrtf(v1[o] + EPSV);
        g_y[b * KTOT + o * LL + l] = (acc - m1[o]) * s + b1[o];
    }
}

// ---------------------------------------------------------------------------
// Kernel C1: partial h = Y(1024x6144) @ W_fc(6144x200), split-K
// ---------------------------------------------------------------------------
__global__ void kC1(const float* __restrict__ W_fc) {
    int mt = blockIdx.x;
    int ks = blockIdx.y;
    int d = threadIdx.x;
    int b0 = mt * 32;
    int k0 = ks * (KTOT / KSPLIT);
    float acc[32];
#pragma unroll
    for (int i = 0; i < 32; i++) acc[i] = 0.f;
    __shared__ float ys[32][33];
    for (int kc = 0; kc < KTOT / KSPLIT; kc += 32) {
        __syncthreads();
        for (int i = d; i < 32 * 32; i += blockDim.x) {
            int bb = i >> 5, kk = i & 31;
            ys[bb][kk] = g_y[(size_t)(b0 + bb) * KTOT + k0 + kc + kk];
        }
        __syncthreads();
#pragma unroll 4
        for (int kk = 0; kk < 32; kk++) {
            float w = W_fc[(size_t)(k0 + kc + kk) * D + d];
#pragma unroll
            for (int bb = 0; bb < 32; bb++)
                acc[bb] += ys[bb][kk] * w;
        }
    }
    for (int bb = 0; bb < 32; bb++)
        g_hp[(size_t)ks * B * D + (size_t)(b0 + bb) * D + d] = acc[bb];
}

// ---------------------------------------------------------------------------
// Kernel C2: reduce split-K, + b_fc, bn2, relu -> g_hb (bf16, K padded)
// ---------------------------------------------------------------------------
__global__ void kC2(const float* __restrict__ b_fc,
                    const float* __restrict__ g2, const float* __restrict__ b2,
                    const float* __restrict__ m2, const float* __restrict__ v2) {
    int i = blockIdx.x * blockDim.x + threadIdx.x;
    if (i >= B * D) return;
    int b = i / D;
    int d = i % D;
    float s = 0.f;
#pragma unroll
    for (int ks = 0; ks < KSPLIT; ks++) s += g_hp[(size_t)ks * B * D + i];
    s += b_fc[d];
    float sc = g2[d] / sqrtf(v2[d] + EPSV);
    s = (s - m2[d]) * sc + b2[d];
    s = fmaxf(s, 0.f);
    g_hb[b * KP + d] = __float2bfloat16(s);
    if (d < KP - D) g_hb[b * KP + D + d] = __float2bfloat16(0.f);
}

// ---------------------------------------------------------------------------
// convE: E (fp32, NNE x D) -> g_Eb (bf16, NPAD x KP) zero-padded
// ---------------------------------------------------------------------------
__global__ void convE(const float* __restrict__ E) {
    size_t i = (size_t)blockIdx.x * blockDim.x + threadIdx.x;
    if (i >= (size_t)NPAD * KP) return;
    int n = (int)(i / KP);
    int k = (int)(i % KP);
    float v = (n < NNE && k < D) ? E[(size_t)n * D + k] : 0.f;
    g_Eb[i] = __float2bfloat16(v);
}

// ---------------------------------------------------------------------------
// Kernel D: out[m,n] = sigmoid( h[m,:] . E[n,:] + bias[n] )
// BF16 mma m16n8k16; BM=64 x BN=256; 256 thr (2x4 warps; 32x64 per warp)
// 3-stage cp.async ring, one __syncthreads per K-step, float2 stores.
// grid = (B/BM, NPAD/BN)
// ---------------------------------------------------------------------------
__global__ void __launch_bounds__(256, 2)
kD(const float* __restrict__ bias, float* __restrict__ out) {
    __shared__ __align__(16) __nv_bfloat16 As[NSTG][BM][24];
    __shared__ __align__(16) __nv_bfloat16 Bs[NSTG][BN][24];

    const int m0 = blockIdx.x * BM;
    const int n0 = blockIdx.y * BN;
    const int tid = threadIdx.x;
    const int lane = tid & 31;
    const int wid = tid >> 5;
    const int wm = wid >> 2;    // 0..1  -> m offset 32
    const int wn = wid & 3;     // 0..3  -> n offset 64

    float acc[2][8][4];
#pragma unroll
    for (int i = 0; i < 2; i++)
#pragma unroll
        for (int j = 0; j < 8; j++)
#pragma unroll
            for (int c = 0; c < 4; c++) acc[i][j][c] = 0.f;

    const int arow = tid >> 1, ac8 = (tid & 1) * 8;

#define LOAD_STAGE(S, KS)                                                          \
    do {                                                                           \
        if (tid < 128) {                                                           \
            unsigned dst = (unsigned)__cvta_generic_to_shared(&As[S][arow][ac8]);  \
            const __nv_bfloat16* src = &g_hb[(size_t)(m0 + arow) * KP + (KS) + ac8];\
            asm volatile("cp.async.cg.shared.global [%0], [%1], 16;\n"             \
                         :: "r"(dst), "l"(src));                                   \
        }                                                                          \
        _Pragma("unroll")                                                          \
        for (int h = 0; h < 2; h++) {                                              \
            int ch = tid + h * 256;                                                \
            int br = ch >> 1, bc = (ch & 1) * 8;                                   \
            unsigned dst = (unsigned)__cvta_generic_to_shared(&Bs[S][br][bc]);     \
            const __nv_bfloat16* src = &g_Eb[(size_t)(n0 + br) * KP + (KS) + bc];  \
            asm volatile("cp.async.cg.shared.global [%0], [%1], 16;\n"             \
                         :: "r"(dst), "l"(src));                                   \
        }                                                                          \
        asm volatile("cp.async.commit_group;\n" ::);                               \
    } while (0)

    LOAD_STAGE(0, 0);
    LOAD_STAGE(1, 16);

    for (int s = 0; s < NKSTEP; s++) {
        asm volatile("cp.async.wait_group 1;\n" ::);
        __syncthreads();

        if (s + 2 < NKSTEP) {
            const int st2 = (s + 2) % NSTG;
            const int ks2 = (s + 2) * 16;
            LOAD_STAGE(st2, ks2);
        } else {
            asm volatile("cp.async.commit_group;\n" ::);
        }

        const int st = s % NSTG;
        unsigned a[2][4];
        unsigned bfr[8][2];

#pragma unroll
        for (int mi = 0; mi < 2; mi++) {
            unsigned addr = (unsigned)__cvta_generic_to_shared(
                &As[st][wm * 32 + mi * 16 + (lane & 15)][(lane >> 4) * 8]);
            asm volatile("ldmatrix.sync.aligned.m8n8.x4.shared.b16 {%0,%1,%2,%3}, [%4];"
                         : "=r"(a[mi][0]), "=r"(a[mi][1]), "=r"(a[mi][2]), "=r"(a[mi][3])
                         : "r"(addr));
        }
#pragma unroll
        for (int p = 0; p < 4; p++) {
            unsigned addr = (unsigned)__cvta_generic_to_shared(
                &Bs[st][wn * 64 + p * 16 + ((lane >> 4) << 3) + (lane & 7)]
                   [((lane >> 3) & 1) * 8]);
            asm volatile("ldmatrix.sync.aligned.m8n8.x4.shared.b16 {%0,%1,%2,%3}, [%4];"
                         : "=r"(bfr[2 * p][0]), "=r"(bfr[2 * p][1]),
                           "=r"(bfr[2 * p + 1][0]), "=r"(bfr[2 * p + 1][1])
                         : "r"(addr));
        }

#pragma unroll
        for (int mi = 0; mi < 2; mi++)
#pragma unroll
            for (int ni = 0; ni < 8; ni++) {
                asm volatile(
                    "mma.sync.aligned.m16n8k16.row.col.f32.bf16.bf16.f32 "
                    "{%0,%1,%2,%3}, {%4,%5,%6,%7}, {%8,%9}, {%0,%1,%2,%3};"
                    : "+f"(acc[mi][ni][0]), "+f"(acc[mi][ni][1]),
                      "+f"(acc[mi][ni][2]), "+f"(acc[mi][ni][3])
                    : "r"(a[mi][0]), "r"(a[mi][1]), "r"(a[mi][2]), "r"(a[mi][3]),
                      "r"(bfr[ni][0]), "r"(bfr[ni][1]));
            }
    }

    // epilogue: bias + sigmoid, float2 stores (n even, NNE even)
    const int rin = lane >> 2;
    const int cin = (lane & 3) * 2;
#pragma unroll
    for (int ni = 0; ni < 8; ni++) {
        int n = n0 + wn * 64 + ni * 8 + cin;
        if (n >= NNE) continue;
        float2 bz = *(const float2*)(bias + n);
#pragma unroll
        for (int mi = 0; mi < 2; mi++) {
            int m = m0 + wm * 32 + mi * 16 + rin;
            float2 o0, o1;
            o0.x = 1.f / (1.f + __expf(-(acc[mi][ni][0] + bz.x)));
            o0.y = 1.f / (1.f + __expf(-(acc[mi][ni][1] + bz.y)));
            o1.x = 1.f / (1.f + __expf(-(acc[mi][ni][2] + bz.x)));
            o1.y = 1.f / (1.f + __expf(-(acc[mi][ni][3] + bz.y)));
            *(float2*)(out + (size_t)m * NNE + n)       = o0;
            *(float2*)(out + (size_t)(m + 8) * NNE + n) = o1;
        }
    }
#undef LOAD_STAGE
}

// ---------------------------------------------------------------------------
extern "C" void kernel_launch(void* const* d_in, const int* in_sizes, int n_in,
                              void* d_out, int out_size) {
    const int*   e1_idx = (const int*)d_in[0];
    const int*   r_idx  = (const int*)d_in[1];
    const float* E      = (const float*)d_in[2];
    const float* R      = (const float*)d_in[3];
    const float* W_fc   = (const float*)d_in[4];
    const float* b_fc   = (const float*)d_in[5];
    const float* W_fc1  = (const float*)d_in[6];
    const float* b_fc1  = (const float*)d_in[7];
    const float* bn0_g  = (const float*)d_in[8];
    const float* bn0_b  = (const float*)d_in[9];
    const float* bn0_m  = (const float*)d_in[10];
    const float* bn0_v  = (const float*)d_in[11];
    const float* bn1_g  = (const float*)d_in[12];
    const float* bn1_b  = (const float*)d_in[13];
    const float* bn1_m  = (const float*)d_in[14];
    const float* bn1_v  = (const float*)d_in[15];
    const float* bn2_g  = (const float*)d_in[16];
    const float* bn2_b  = (const float*)d_in[17];
    const float* bn2_m  = (const float*)d_in[18];
    const float* bn2_v  = (const float*)d_in[19];
    const float* bvec   = (const float*)d_in[20];
    float* out = (float*)d_out;

    kA<<<B, KFW>>>(e1_idx, r_idx, E, R, W_fc1, b_fc1, bn0_g, bn0_b, bn0_m, bn0_v);
    kB<<<B, LL>>>(bn1_g, bn1_b, bn1_m, bn1_v);
    kC1<<<dim3(B / 32, KSPLIT), D>>>(W_fc);
    kC2<<<(B * D + 255) / 256, 256>>>(b_fc, bn2_g, bn2_b, bn2_m, bn2_v);

    convE<<<(int)(((size_t)NPAD * KP + 255) / 256), 256>>>(E);

    dim3 gD(B / BM, NPAD / BN);
    kD<<<gD, 256>>>(bvec, out);
}

// round 6
// speedup vs baseline: 4.0317x; 1.2853x over previous
#include <cuda_runtime.h>
#include <cuda_bf16.h>
#include <cstdint>
#include <math.h>

#define B 1024
#define NNE 100000
#define NPAD 100096          // padded rows of E (multiple of 256)
#define D 200
#define KP 208               // K padded to multiple of 16 (kD)
#define OC 32
#define FW 9
#define LL 192               // D - FW + 1
#define KTOT (OC * LL)       // 6144
#define KFW (OC * FW)        // 288
#define KSPLIT 8
#define NPW 256              // padded output cols of kC1m (>= D, mult of 128)
#define EPSV 1e-5f

// kD tiling
#define BM 64
#define BN 256
#define NKSTEP 13            // KP / 16
#define NSTG 3

// kC1m tiling
#define C_BM 64
#define C_BN 128
#define C_STEPS (KTOT / KSPLIT / 16)   // 48

// scratch (no allocations allowed)
__device__ float g_x[B * D];
__device__ float g_k[B * KFW];
__device__ __nv_bfloat16 g_yb[B * KTOT];
__device__ __nv_bfloat16 g_Wb[(size_t)NPW * KTOT];
__device__ float g_hp[(size_t)KSPLIT * B * NPW];
__device__ __nv_bfloat16 g_hb[B * KP];
__device__ __nv_bfloat16 g_Eb[(size_t)NPAD * KP];

// ---------------------------------------------------------------------------
// convE: E (fp32, NNE x D) -> g_Eb (bf16, NPAD x KP) zero-padded
// ---------------------------------------------------------------------------
__global__ void convE(const float* __restrict__ E) {
    size_t i = (size_t)blockIdx.x * blockDim.x + threadIdx.x;
    if (i >= (size_t)NPAD * KP) return;
    int n = (int)(i / KP);
    int k = (int)(i % KP);
    float v = (n < NNE && k < D) ? E[(size_t)n * D + k] : 0.f;
    g_Eb[i] = __float2bfloat16(v);
}

// ---------------------------------------------------------------------------
// convW: W_fc (fp32, KTOT x D) -> g_Wb (bf16, NPW x KTOT) transposed, padded
// ---------------------------------------------------------------------------
__global__ void convW(const float* __restrict__ W_fc) {
    size_t i = (size_t)blockIdx.x * blockDim.x + threadIdx.x;
    if (i >= (size_t)NPW * KTOT) return;
    int k = (int)(i / NPW);
    int n = (int)(i % NPW);
    float v = (n < D) ? W_fc[(size_t)k * D + n] : 0.f;
    g_Wb[(size_t)n * KTOT + k] = __float2bfloat16(v);
}

// ---------------------------------------------------------------------------
// Kernel A (batched x8): x = bn0(E[e1_idx]) ; k = R[r_idx] @ W_fc1 + b_fc1
// grid = B/8, block = 288
// ---------------------------------------------------------------------------
__global__ void kA(const int* __restrict__ e1_idx, const int* __restrict__ r_idx,
                   const float* __restrict__ E, const float* __restrict__ R,
                   const float* __restrict__ W_fc1, const float* __restrict__ b_fc1,
                   const float* __restrict__ pg0, const float* __restrict__ pb0,
                   const float* __restrict__ pm0, const float* __restrict__ pv0) {
    int bbase = blockIdx.x * 8;
    int t = threadIdx.x;
    __shared__ float rs[8][D];
    float s0 = pg0[0] / sqrtf(pv0[0] + EPSV);
    float bb0 = pb0[0], mm0 = pm0[0];
    for (int i = t; i < 8 * D; i += KFW) {
        int g = i / D, d = i % D;
        int bi = bbase + g;
        rs[g][d] = R[(size_t)r_idx[bi] * D + d];
        g_x[bi * D + d] = (E[(size_t)e1_idx[bi] * D + d] - mm0) * s0 + bb0;
    }
    __syncthreads();
    float acc[8];
#pragma unroll
    for (int g = 0; g < 8; g++) acc[g] = b_fc1[t];
    for (int d = 0; d < D; d++) {
        float w = W_fc1[d * KFW + t];
#pragma unroll
        for (int g = 0; g < 8; g++) acc[g] += rs[g][d] * w;
    }
#pragma unroll
    for (int g = 0; g < 8; g++)
        g_k[(bbase + g) * KFW + t] = acc[g];
}

// ---------------------------------------------------------------------------
// Kernel B: y[b,o,l] = sum_w x[b,l+w]*k[b,o,w]; bn1 -> g_yb (bf16)
// ---------------------------------------------------------------------------
__global__ void kB(const float* __restrict__ g1, const float* __restrict__ b1,
                   const float* __restrict__ m1, const float* __restrict__ v1) {
    int b = blockIdx.x;
    int l = threadIdx.x;
    __shared__ float xs[D];
    __shared__ float ks[KFW];
    for (int i = l; i < D; i += blockDim.x)   xs[i] = g_x[b * D + i];
    for (int i = l; i < KFW; i += blockDim.x) ks[i] = g_k[b * KFW + i];
    __syncthreads();
    float xv[FW];
#pragma unroll
    for (int w = 0; w < FW; w++) xv[w] = xs[l + w];
    for (int o = 0; o < OC; o++) {
        float acc = 0.f;
#pragma unroll
        for (int w = 0; w < FW; w++) acc += xv[w] * ks[o * FW + w];
        float s = g1[o] / sqrtf(v1[o] + EPSV);
        g_yb[b * KTOT + o * LL + l] = __float2bfloat16((acc - m1[o]) * s + b1[o]);
    }
}

// ---------------------------------------------------------------------------
// Kernel C1m: partial h = Y(1024x6144,bf16) @ Wb^T (NPWx6144,bf16), split-K=8
// BF16 mma m16n8k16; C_BM=64 x C_BN=128; 8 warps (2x4), warp 32x32.
// 3-stage cp.async ring. grid = (16, 2, 8). Partials fp32 -> g_hp.
// ---------------------------------------------------------------------------
__global__ void __launch_bounds__(256)
kC1m() {
    __shared__ __align__(16) __nv_bfloat16 As[NSTG][C_BM][24];
    __shared__ __align__(16) __nv_bfloat16 Bs[NSTG][C_BN][24];

    const int m0 = blockIdx.x * C_BM;
    const int n0 = blockIdx.y * C_BN;
    const int ks = blockIdx.z;
    const int k0 = ks * (KTOT / KSPLIT);
    const int tid = threadIdx.x;
    const int lane = tid & 31;
    const int wid = tid >> 5;
    const int wm = wid >> 2;
    const int wn = wid & 3;

    float acc[2][4][4];
#pragma unroll
    for (int i = 0; i < 2; i++)
#pragma unroll
        for (int j = 0; j < 4; j++)
#pragma unroll
            for (int c = 0; c < 4; c++) acc[i][j][c] = 0.f;

    const int arow = tid >> 1, ac8 = (tid & 1) * 8;

#define LOAD_C(S, KS)                                                            \
    do {                                                                         \
        if (tid < 128) {                                                         \
            unsigned dst = (unsigned)__cvta_generic_to_shared(&As[S][arow][ac8]);\
            const __nv_bfloat16* src = &g_yb[(size_t)(m0 + arow) * KTOT + k0 + (KS) + ac8];\
            asm volatile("cp.async.cg.shared.global [%0], [%1], 16;\n"           \
                         :: "r"(dst), "l"(src));                                 \
        }                                                                        \
        {                                                                        \
            unsigned dst = (unsigned)__cvta_generic_to_shared(&Bs[S][arow][ac8]);\
            const __nv_bfloat16* src = &g_Wb[(size_t)(n0 + arow) * KTOT + k0 + (KS) + ac8];\
            asm volatile("cp.async.cg.shared.global [%0], [%1], 16;\n"           \
                         :: "r"(dst), "l"(src));                                 \
        }                                                                        \
        asm volatile("cp.async.commit_group;\n" ::);                             \
    } while (0)

    LOAD_C(0, 0);
    LOAD_C(1, 16);

    int st = 0;
    int stp = 2;
    for (int s = 0; s < C_STEPS; s++) {
        asm volatile("cp.async.wait_group 1;\n" ::);
        __syncthreads();

        if (s + 2 < C_STEPS) {
            LOAD_C(stp, (s + 2) * 16);
        } else {
            asm volatile("cp.async.commit_group;\n" ::);
        }

        unsigned a[2][4];
        unsigned bfr[4][2];
#pragma unroll
        for (int mi = 0; mi < 2; mi++) {
            unsigned addr = (unsigned)__cvta_generic_to_shared(
                &As[st][wm * 32 + mi * 16 + (lane & 15)][(lane >> 4) * 8]);
            asm volatile("ldmatrix.sync.aligned.m8n8.x4.shared.b16 {%0,%1,%2,%3}, [%4];"
                         : "=r"(a[mi][0]), "=r"(a[mi][1]), "=r"(a[mi][2]), "=r"(a[mi][3])
                         : "r"(addr));
        }
#pragma unroll
        for (int p = 0; p < 2; p++) {
            unsigned addr = (unsigned)__cvta_generic_to_shared(
                &Bs[st][wn * 32 + p * 16 + ((lane >> 4) << 3) + (lane & 7)]
                   [((lane >> 3) & 1) * 8]);
            asm volatile("ldmatrix.sync.aligned.m8n8.x4.shared.b16 {%0,%1,%2,%3}, [%4];"
                         : "=r"(bfr[2 * p][0]), "=r"(bfr[2 * p][1]),
                           "=r"(bfr[2 * p + 1][0]), "=r"(bfr[2 * p + 1][1])
                         : "r"(addr));
        }
#pragma unroll
        for (int mi = 0; mi < 2; mi++)
#pragma unroll
            for (int ni = 0; ni < 4; ni++) {
                asm volatile(
                    "mma.sync.aligned.m16n8k16.row.col.f32.bf16.bf16.f32 "
                    "{%0,%1,%2,%3}, {%4,%5,%6,%7}, {%8,%9}, {%0,%1,%2,%3};"
                    : "+f"(acc[mi][ni][0]), "+f"(acc[mi][ni][1]),
                      "+f"(acc[mi][ni][2]), "+f"(acc[mi][ni][3])
                    : "r"(a[mi][0]), "r"(a[mi][1]), "r"(a[mi][2]), "r"(a[mi][3]),
                      "r"(bfr[ni][0]), "r"(bfr[ni][1]));
            }
        st = (st == NSTG - 1) ? 0 : st + 1;
        stp = (stp == NSTG - 1) ? 0 : stp + 1;
    }

    // store partials (no guards: NPW covers all n)
    const int rin = lane >> 2;
    const int cin = (lane & 3) * 2;
    float* hp = g_hp + (size_t)ks * B * NPW;
#pragma unroll
    for (int mi = 0; mi < 2; mi++) {
#pragma unroll
        for (int ni = 0; ni < 4; ni++) {
            int m = m0 + wm * 32 + mi * 16 + rin;
            int n = n0 + wn * 32 + ni * 8 + cin;
            float2 v0 = make_float2(acc[mi][ni][0], acc[mi][ni][1]);
            float2 v1 = make_float2(acc[mi][ni][2], acc[mi][ni][3]);
            *(float2*)(hp + (size_t)m * NPW + n)       = v0;
            *(float2*)(hp + (size_t)(m + 8) * NPW + n) = v1;
        }
    }
#undef LOAD_C
}

// ---------------------------------------------------------------------------
// Kernel C2: reduce split-K, + b_fc, bn2, relu -> g_hb (bf16, K padded)
// ---------------------------------------------------------------------------
__global__ void kC2(const float* __restrict__ b_fc,
                    const float* __restrict__ g2, const float* __restrict__ b2,
                    const float* __restrict__ m2, const float* __restrict__ v2) {
    int i = blockIdx.x * blockDim.x + threadIdx.x;
    if (i >= B * D) return;
    int b = i / D;
    int d = i % D;
    float s = 0.f;
#pragma unroll
    for (int ks = 0; ks < KSPLIT; ks++)
        s += g_hp[(size_t)ks * B * NPW + (size_t)b * NPW + d];
    s += b_fc[d];
    float sc = g2[d] / sqrtf(v2[d] + EPSV);
    s = (s - m2[d]) * sc + b2[d];
    s = fmaxf(s, 0.f);
    g_hb[b * KP + d] = __float2bfloat16(s);
    if (d < KP - D) g_hb[b * KP + D + d] = __float2bfloat16(0.f);
}

// ---------------------------------------------------------------------------
// Kernel D: out[m,n] = sigmoid( h[m,:] . E[n,:] + bias[n] )
// BF16 mma m16n8k16; BM=64 x BN=256; 256 thr (2x4 warps; 32x64 per warp)
// 3-stage cp.async ring, one __syncthreads per K-step, float2 stores.
// grid = (B/BM, NPAD/BN)
// ---------------------------------------------------------------------------
__global__ void __launch_bounds__(256, 2)
kD(const float* __restrict__ bias, float* __restrict__ out) {
    __shared__ __align__(16) __nv_bfloat16 As[NSTG][BM][24];
    __shared__ __align__(16) __nv_bfloat16 Bs[NSTG][BN][24];

    const int m0 = blockIdx.x * BM;
    const int n0 = blockIdx.y * BN;
    const int tid = threadIdx.x;
    const int lane = tid & 31;
    const int wid = tid >> 5;
    const int wm = wid >> 2;    // 0..1  -> m offset 32
    const int wn = wid & 3;     // 0..3  -> n offset 64

    float acc[2][8][4];
#pragma unroll
    for (int i = 0; i < 2; i++)
#pragma unroll
        for (int j = 0; j < 8; j++)
#pragma unroll
            for (int c = 0; c < 4; c++) acc[i][j][c] = 0.f;

    const int arow = tid >> 1, ac8 = (tid & 1) * 8;

#define LOAD_STAGE(S, KS)                                                          \
    do {                                                                           \
        if (tid < 128) {                                                           \
            unsigned dst = (unsigned)__cvta_generic_to_shared(&As[S][arow][ac8]);  \
            const __nv_bfloat16* src = &g_hb[(size_t)(m0 + arow) * KP + (KS) + ac8];\
            asm volatile("cp.async.cg.shared.global [%0], [%1], 16;\n"             \
                         :: "r"(dst), "l"(src));                                   \
        }                                                                          \
        _Pragma("unroll")                                                          \
        for (int h = 0; h < 2; h++) {                                              \
            int ch = tid + h * 256;                                                \
            int br = ch >> 1, bc = (ch & 1) * 8;                                   \
            unsigned dst = (unsigned)__cvta_generic_to_shared(&Bs[S][br][bc]);     \
            const __nv_bfloat16* src = &g_Eb[(size_t)(n0 + br) * KP + (KS) + bc];  \
            asm volatile("cp.async.cg.shared.global [%0], [%1], 16;\n"             \
                         :: "r"(dst), "l"(src));                                   \
        }                                                                          \
        asm volatile("cp.async.commit_group;\n" ::);                               \
    } while (0)

    LOAD_STAGE(0, 0);
    LOAD_STAGE(1, 16);

    int st = 0;
    int stp = 2;
    for (int s = 0; s < NKSTEP; s++) {
        asm volatile("cp.async.wait_group 1;\n" ::);
        __syncthreads();

        if (s + 2 < NKSTEP) {
            LOAD_STAGE(stp, (s + 2) * 16);
        } else {
            asm volatile("cp.async.commit_group;\n" ::);
        }

        unsigned a[2][4];
        unsigned bfr[8][2];

#pragma unroll
        for (int mi = 0; mi < 2; mi++) {
            unsigned addr = (unsigned)__cvta_generic_to_shared(
                &As[st][wm * 32 + mi * 16 + (lane & 15)][(lane >> 4) * 8]);
            asm volatile("ldmatrix.sync.aligned.m8n8.x4.shared.b16 {%0,%1,%2,%3}, [%4];"
                         : "=r"(a[mi][0]), "=r"(a[mi][1]), "=r"(a[mi][2]), "=r"(a[mi][3])
                         : "r"(addr));
        }
#pragma unroll
        for (int p = 0; p < 4; p++) {
            unsigned addr = (unsigned)__cvta_generic_to_shared(
                &Bs[st][wn * 64 + p * 16 + ((lane >> 4) << 3) + (lane & 7)]
                   [((lane >> 3) & 1) * 8]);
            asm volatile("ldmatrix.sync.aligned.m8n8.x4.shared.b16 {%0,%1,%2,%3}, [%4];"
                         : "=r"(bfr[2 * p][0]), "=r"(bfr[2 * p][1]),
                           "=r"(bfr[2 * p + 1][0]), "=r"(bfr[2 * p + 1][1])
                         : "r"(addr));
        }

#pragma unroll
        for (int mi = 0; mi < 2; mi++)
#pragma unroll
            for (int ni = 0; ni < 8; ni++) {
                asm volatile(
                    "mma.sync.aligned.m16n8k16.row.col.f32.bf16.bf16.f32 "
                    "{%0,%1,%2,%3}, {%4,%5,%6,%7}, {%8,%9}, {%0,%1,%2,%3};"
                    : "+f"(acc[mi][ni][0]), "+f"(acc[mi][ni][1]),
                      "+f"(acc[mi][ni][2]), "+f"(acc[mi][ni][3])
                    : "r"(a[mi][0]), "r"(a[mi][1]), "r"(a[mi][2]), "r"(a[mi][3]),
                      "r"(bfr[ni][0]), "r"(bfr[ni][1]));
            }
        st = (st == NSTG - 1) ? 0 : st + 1;
        stp = (stp == NSTG - 1) ? 0 : stp + 1;
    }

    // epilogue: bias + sigmoid, float2 stores (n even, NNE even)
    const int rin = lane >> 2;
    const int cin = (lane & 3) * 2;
#pragma unroll
    for (int ni = 0; ni < 8; ni++) {
        int n = n0 + wn * 64 + ni * 8 + cin;
        if (n >= NNE) continue;
        float2 bz = *(const float2*)(bias + n);
#pragma unroll
        for (int mi = 0; mi < 2; mi++) {
            int m = m0 + wm * 32 + mi * 16 + rin;
            float2 o0, o1;
            o0.x = 1.f / (1.f + __expf(-(acc[mi][ni][0] + bz.x)));
            o0.y = 1.f / (1.f + __expf(-(acc[mi][ni][1] + bz.y)));
            o1.x = 1.f / (1.f + __expf(-(acc[mi][ni][2] + bz.x)));
            o1.y = 1.f / (1.f + __expf(-(acc[mi][ni][3] + bz.y)));
            *(float2*)(out + (size_t)m * NNE + n)       = o0;
            *(float2*)(out + (size_t)(m + 8) * NNE + n) = o1;
        }
    }
#undef LOAD_STAGE
}

// ---------------------------------------------------------------------------
extern "C" void kernel_launch(void* const* d_in, const int* in_sizes, int n_in,
                              void* d_out, int out_size) {
    const int*   e1_idx = (const int*)d_in[0];
    const int*   r_idx  = (const int*)d_in[1];
    const float* E      = (const float*)d_in[2];
    const float* R      = (const float*)d_in[3];
    const float* W_fc   = (const float*)d_in[4];
    const float* b_fc   = (const float*)d_in[5];
    const float* W_fc1  = (const float*)d_in[6];
    const float* b_fc1  = (const float*)d_in[7];
    const float* bn0_g  = (const float*)d_in[8];
    const float* bn0_b  = (const float*)d_in[9];
    const float* bn0_m  = (const float*)d_in[10];
    const float* bn0_v  = (const float*)d_in[11];
    const float* bn1_g  = (const float*)d_in[12];
    const float* bn1_b  = (const float*)d_in[13];
    const float* bn1_m  = (const float*)d_in[14];
    const float* bn1_v  = (const float*)d_in[15];
    const float* bn2_g  = (const float*)d_in[16];
    const float* bn2_b  = (const float*)d_in[17];
    const float* bn2_m  = (const float*)d_in[18];
    const float* bn2_v  = (const float*)d_in[19];
    const float* bvec   = (const float*)d_in[20];
    float* out = (float*)d_out;

    convE<<<(int)(((size_t)NPAD * KP + 255) / 256), 256>>>(E);
    convW<<<(int)(((size_t)NPW * KTOT + 255) / 256), 256>>>(W_fc);
    kA<<<B / 8, KFW>>>(e1_idx, r_idx, E, R, W_fc1, b_fc1, bn0_g, bn0_b, bn0_m, bn0_v);
    kB<<<B, LL>>>(bn1_g, bn1_b, bn1_m, bn1_v);
    kC1m<<<dim3(B / C_BM, NPW / C_BN, KSPLIT), 256>>>();
    kC2<<<(B * D + 255) / 256, 256>>>(b_fc, bn2_g, bn2_b, bn2_m, bn2_v);

    dim3 gD(B / BM, NPAD / BN);
    kD<<<gD, 256>>>(bvec, out);
}

// round 7
// speedup vs baseline: 4.4150x; 1.0951x over previous
#include <cuda_runtime.h>
#include <cuda_fp16.h>
#include <cstdint>
#include <math.h>

#define B 1024
#define NNE 100000
#define NPAD 100096          // padded rows of E (multiple of 256)
#define D 200
#define KP 224               // K padded to multiple of 32 (kD, 7 chunks)
#define OC 32
#define FW 9
#define LL 192               // D - FW + 1
#define KTOT (OC * LL)       // 6144
#define KFW (OC * FW)        // 288
#define KSPLIT 8
#define NPW 256              // padded output cols of kC1m
#define EPSV 1e-5f

// kD tiling
#define BM 64
#define BN 256
#define NK 7                 // KP / 32
#define NSTG 3
#define KD_SMEM (NSTG * (BM + BN) * 40 * 2)   // 76800 B

// kC1m tiling
#define C_BM 64
#define C_BN 128
#define C_STEPS (KTOT / KSPLIT / 16)   // 48

// scratch (no allocations allowed)
__device__ __half g_yb[B * KTOT];
__device__ __half g_Wb[(size_t)NPW * KTOT];
__device__ float g_hp[(size_t)KSPLIT * B * NPW];
__device__ __half g_hb[B * KP];
__device__ __half g_Eb[(size_t)NPAD * KP];

// ---------------------------------------------------------------------------
// convE: E (fp32, NNE x D) -> g_Eb (fp16, NPAD x KP) zero-padded
// ---------------------------------------------------------------------------
__global__ void convE(const float* __restrict__ E) {
    size_t i = (size_t)blockIdx.x * blockDim.x + threadIdx.x;
    if (i >= (size_t)NPAD * KP) return;
    int n = (int)(i / KP);
    int k = (int)(i % KP);
    float v = (n < NNE && k < D) ? E[(size_t)n * D + k] : 0.f;
    g_Eb[i] = __float2half(v);
}

// ---------------------------------------------------------------------------
// convW: W_fc (fp32, KTOT x D) -> g_Wb (fp16, NPW x KTOT) transposed, padded
// ---------------------------------------------------------------------------
__global__ void convW(const float* __restrict__ W_fc) {
    size_t i = (size_t)blockIdx.x * blockDim.x + threadIdx.x;
    if (i >= (size_t)NPW * KTOT) return;
    int k = (int)(i / NPW);
    int n = (int)(i % NPW);
    float v = (n < D) ? W_fc[(size_t)k * D + n] : 0.f;
    g_Wb[(size_t)n * KTOT + k] = __float2half(v);
}

// ---------------------------------------------------------------------------
// kAB (fused, batched x8): x = bn0(E[e1]); k = R[r] @ W_fc1 + b_fc1;
//   y[b,o,l] = bn1(sum_w x[b,l+w]*k[b,o,w]) -> g_yb (fp16)
// grid = B/8, block = 288
// ---------------------------------------------------------------------------
__global__ void kAB(const int* __restrict__ e1_idx, const int* __restrict__ r_idx,
                    const float* __restrict__ E, const float* __restrict__ R,
                    const float* __restrict__ W_fc1, const float* __restrict__ b_fc1,
                    const float* __restrict__ pg0, const float* __restrict__ pb0,
                    const float* __restrict__ pm0, const float* __restrict__ pv0,
                    const float* __restrict__ g1, const float* __restrict__ b1,
                    const float* __restrict__ m1, const float* __restrict__ v1) {
    int bbase = blockIdx.x * 8;
    int t = threadIdx.x;
    __shared__ float rs[8][D];
    __shared__ float xs[8][D];
    __shared__ float kb[8][KFW];
    float s0 = pg0[0] / sqrtf(pv0[0] + EPSV);
    float bb0 = pb0[0], mm0 = pm0[0];
    for (int i = t; i < 8 * D; i += KFW) {
        int g = i / D, d = i % D;
        int bi = bbase + g;
        rs[g][d] = R[(size_t)r_idx[bi] * D + d];
        xs[g][d] = (E[(size_t)e1_idx[bi] * D + d] - mm0) * s0 + bb0;
    }
    __syncthreads();
    {
        float acc[8];
#pragma unroll
        for (int g = 0; g < 8; g++) acc[g] = b_fc1[t];
        for (int d = 0; d < D; d++) {
            float w = W_fc1[d * KFW + t];
#pragma unroll
            for (int g = 0; g < 8; g++) acc[g] += rs[g][d] * w;
        }
#pragma unroll
        for (int g = 0; g < 8; g++) kb[g][t] = acc[g];
    }
    __syncthreads();
    if (t < LL) {
        int l = t;
        for (int o = 0; o < OC; o++) {
            float s = g1[o] / sqrtf(v1[o] + EPSV);
            float mo = m1[o], bo = b1[o];
#pragma unroll
            for (int g = 0; g < 8; g++) {
                float acc = 0.f;
#pragma unroll
                for (int w = 0; w < FW; w++) acc += xs[g][l + w] * kb[g][o * FW + w];
                g_yb[(bbase + g) * KTOT + o * LL + l] = __float2half((acc - mo) * s + bo);
            }
        }
    }
}

// ---------------------------------------------------------------------------
// Kernel C1m: partial h = Y(1024x6144,fp16) @ Wb^T (NPWx6144,fp16), split-K=8
// FP16 mma m16n8k16; C_BM=64 x C_BN=128; 8 warps (2x4), warp 32x32.
// ---------------------------------------------------------------------------
__global__ void __launch_bounds__(256)
kC1m() {
    __shared__ __align__(16) __half As[NSTG][C_BM][24];
    __shared__ __align__(16) __half Bs[NSTG][C_BN][24];

    const int m0 = blockIdx.x * C_BM;
    const int n0 = blockIdx.y * C_BN;
    const int ks = blockIdx.z;
    const int k0 = ks * (KTOT / KSPLIT);
    const int tid = threadIdx.x;
    const int lane = tid & 31;
    const int wid = tid >> 5;
    const int wm = wid >> 2;
    const int wn = wid & 3;

    float acc[2][4][4];
#pragma unroll
    for (int i = 0; i < 2; i++)
#pragma unroll
        for (int j = 0; j < 4; j++)
#pragma unroll
            for (int c = 0; c < 4; c++) acc[i][j][c] = 0.f;

    const int arow = tid >> 1, ac8 = (tid & 1) * 8;

#define LOAD_C(S, KS)                                                            \
    do {                                                                         \
        if (tid < 128) {                                                         \
            unsigned dst = (unsigned)__cvta_generic_to_shared(&As[S][arow][ac8]);\
            const __half* src = &g_yb[(size_t)(m0 + arow) * KTOT + k0 + (KS) + ac8];\
            asm volatile("cp.async.cg.shared.global [%0], [%1], 16;\n"           \
                         :: "r"(dst), "l"(src));                                 \
        }                                                                        \
        {                                                                        \
            unsigned dst = (unsigned)__cvta_generic_to_shared(&Bs[S][arow][ac8]);\
            const __half* src = &g_Wb[(size_t)(n0 + arow) * KTOT + k0 + (KS) + ac8];\
            asm volatile("cp.async.cg.shared.global [%0], [%1], 16;\n"           \
                         :: "r"(dst), "l"(src));                                 \
        }                                                                        \
        asm volatile("cp.async.commit_group;\n" ::);                             \
    } while (0)

    LOAD_C(0, 0);
    LOAD_C(1, 16);

    int st = 0;
    int stp = 2;
    for (int s = 0; s < C_STEPS; s++) {
        asm volatile("cp.async.wait_group 1;\n" ::);
        __syncthreads();

        if (s + 2 < C_STEPS) {
            LOAD_C(stp, (s + 2) * 16);
        } else {
            asm volatile("cp.async.commit_group;\n" ::);
        }

        unsigned a[2][4];
        unsigned bfr[4][2];
#pragma unroll
        for (int mi = 0; mi < 2; mi++) {
            unsigned addr = (unsigned)__cvta_generic_to_shared(
                &As[st][wm * 32 + mi * 16 + (lane & 15)][(lane >> 4) * 8]);
            asm volatile("ldmatrix.sync.aligned.m8n8.x4.shared.b16 {%0,%1,%2,%3}, [%4];"
                         : "=r"(a[mi][0]), "=r"(a[mi][1]), "=r"(a[mi][2]), "=r"(a[mi][3])
                         : "r"(addr));
        }
#pragma unroll
        for (int p = 0; p < 2; p++) {
            unsigned addr = (unsigned)__cvta_generic_to_shared(
                &Bs[st][wn * 32 + p * 16 + ((lane >> 4) << 3) + (lane & 7)]
                   [((lane >> 3) & 1) * 8]);
            asm volatile("ldmatrix.sync.aligned.m8n8.x4.shared.b16 {%0,%1,%2,%3}, [%4];"
                         : "=r"(bfr[2 * p][0]), "=r"(bfr[2 * p][1]),
                           "=r"(bfr[2 * p + 1][0]), "=r"(bfr[2 * p + 1][1])
                         : "r"(addr));
        }
#pragma unroll
        for (int mi = 0; mi < 2; mi++)
#pragma unroll
            for (int ni = 0; ni < 4; ni++) {
                asm volatile(
                    "mma.sync.aligned.m16n8k16.row.col.f32.f16.f16.f32 "
                    "{%0,%1,%2,%3}, {%4,%5,%6,%7}, {%8,%9}, {%0,%1,%2,%3};"
                    : "+f"(acc[mi][ni][0]), "+f"(acc[mi][ni][1]),
                      "+f"(acc[mi][ni][2]), "+f"(acc[mi][ni][3])
                    : "r"(a[mi][0]), "r"(a[mi][1]), "r"(a[mi][2]), "r"(a[mi][3]),
                      "r"(bfr[ni][0]), "r"(bfr[ni][1]));
            }
        st = (st == NSTG - 1) ? 0 : st + 1;
        stp = (stp == NSTG - 1) ? 0 : stp + 1;
    }

    const int rin = lane >> 2;
    const int cin = (lane & 3) * 2;
    float* hp = g_hp + (size_t)ks * B * NPW;
#pragma unroll
    for (int mi = 0; mi < 2; mi++) {
#pragma unroll
        for (int ni = 0; ni < 4; ni++) {
            int m = m0 + wm * 32 + mi * 16 + rin;
            int n = n0 + wn * 32 + ni * 8 + cin;
            float2 v0 = make_float2(acc[mi][ni][0], acc[mi][ni][1]);
            float2 v1 = make_float2(acc[mi][ni][2], acc[mi][ni][3]);
            *(float2*)(hp + (size_t)m * NPW + n)       = v0;
            *(float2*)(hp + (size_t)(m + 8) * NPW + n) = v1;
        }
    }
#undef LOAD_C
}

// ---------------------------------------------------------------------------
// Kernel C2: reduce split-K, + b_fc, bn2, relu -> g_hb (fp16, K padded)
// ---------------------------------------------------------------------------
__global__ void kC2(const float* __restrict__ b_fc,
                    const float* __restrict__ g2, const float* __restrict__ b2,
                    const float* __restrict__ m2, const float* __restrict__ v2) {
    int i = blockIdx.x * blockDim.x + threadIdx.x;
    if (i >= B * D) return;
    int b = i / D;
    int d = i % D;
    float s = 0.f;
#pragma unroll
    for (int ks = 0; ks < KSPLIT; ks++)
        s += g_hp[(size_t)ks * B * NPW + (size_t)b * NPW + d];
    s += b_fc[d];
    float sc = g2[d] / sqrtf(v2[d] + EPSV);
    s = (s - m2[d]) * sc + b2[d];
    s = fmaxf(s, 0.f);
    g_hb[b * KP + d] = __float2half(s);
    if (d < KP - D) g_hb[b * KP + D + d] = __float2half(0.f);
}

// ---------------------------------------------------------------------------
// Kernel D: out[m,n] = sigmoid( h[m,:] . E[n,:] + bias[n] )
// FP16 mma m16n8k16; BM=64 x BN=256; BK=32 (7 stages); 3-stage cp.async ring.
// 256 thr (2x4 warps; 32x64 per warp). Dynamic smem (76.8KB), 2 CTAs/SM.
// grid = (B/BM, NPAD/BN)
// ---------------------------------------------------------------------------
__global__ void __launch_bounds__(256, 2)
kD(const float* __restrict__ bias, float* __restrict__ out) {
    extern __shared__ __align__(16) __half dsm[];
    __half* Asm = dsm;                       // [NSTG][BM][40]
    __half* Bsm = dsm + NSTG * BM * 40;      // [NSTG][BN][40]

    const int m0 = blockIdx.x * BM;
    const int n0 = blockIdx.y * BN;
    const int tid = threadIdx.x;
    const int lane = tid & 31;
    const int wid = tid >> 5;
    const int wm = wid >> 2;    // 0..1  -> m offset 32
    const int wn = wid & 3;     // 0..3  -> n offset 64

    float acc[2][8][4];
#pragma unroll
    for (int i = 0; i < 2; i++)
#pragma unroll
        for (int j = 0; j < 8; j++)
#pragma unroll
            for (int c = 0; c < 4; c++) acc[i][j][c] = 0.f;

    const int ar = tid >> 2, ac = (tid & 3) * 8;

#define LOAD_D(S, KS)                                                              \
    do {                                                                           \
        {                                                                          \
            unsigned dst = (unsigned)__cvta_generic_to_shared(                     \
                &Asm[((S) * BM + ar) * 40 + ac]);                                  \
            const __half* src = &g_hb[(size_t)(m0 + ar) * KP + (KS) + ac];         \
            asm volatile("cp.async.cg.shared.global [%0], [%1], 16;\n"             \
                         :: "r"(dst), "l"(src));                                   \
        }                                                                          \
        _Pragma("unroll")                                                          \
        for (int h = 0; h < 4; h++) {                                              \
            int ch = tid + h * 256;                                                \
            int br = ch >> 2, bc = (ch & 3) * 8;                                   \
            unsigned dst = (unsigned)__cvta_generic_to_shared(                     \
                &Bsm[((S) * BN + br) * 40 + bc]);                                  \
            const __half* src = &g_Eb[(size_t)(n0 + br) * KP + (KS) + bc];         \
            asm volatile("cp.async.cg.shared.global [%0], [%1], 16;\n"             \
                         :: "r"(dst), "l"(src));                                   \
        }                                                                          \
        asm volatile("cp.async.commit_group;\n" ::);                               \
    } while (0)

    LOAD_D(0, 0);
    LOAD_D(1, 32);

    int st = 0;
    int stp = 2;
    for (int s = 0; s < NK; s++) {
        asm volatile("cp.async.wait_group 1;\n" ::);
        __syncthreads();

        if (s + 2 < NK) {
            LOAD_D(stp, (s + 2) * 32);
        } else {
            asm volatile("cp.async.commit_group;\n" ::);
        }

#pragma unroll
        for (int ksub = 0; ksub < 2; ksub++) {
            unsigned a[2][4];
            unsigned bfr[8][2];
#pragma unroll
            for (int mi = 0; mi < 2; mi++) {
                unsigned addr = (unsigned)__cvta_generic_to_shared(
                    &Asm[(st * BM + wm * 32 + mi * 16 + (lane & 15)) * 40
                         + ksub * 16 + (lane >> 4) * 8]);
                asm volatile("ldmatrix.sync.aligned.m8n8.x4.shared.b16 {%0,%1,%2,%3}, [%4];"
                             : "=r"(a[mi][0]), "=r"(a[mi][1]), "=r"(a[mi][2]), "=r"(a[mi][3])
                             : "r"(addr));
            }
#pragma unroll
            for (int p = 0; p < 4; p++) {
                unsigned addr = (unsigned)__cvta_generic_to_shared(
                    &Bsm[(st * BN + wn * 64 + p * 16 + ((lane >> 4) << 3) + (lane & 7)) * 40
                         + ksub * 16 + ((lane >> 3) & 1) * 8]);
                asm volatile("ldmatrix.sync.aligned.m8n8.x4.shared.b16 {%0,%1,%2,%3}, [%4];"
                             : "=r"(bfr[2 * p][0]), "=r"(bfr[2 * p][1]),
                               "=r"(bfr[2 * p + 1][0]), "=r"(bfr[2 * p + 1][1])
                             : "r"(addr));
            }
#pragma unroll
            for (int mi = 0; mi < 2; mi++)
#pragma unroll
                for (int ni = 0; ni < 8; ni++) {
                    asm volatile(
                        "mma.sync.aligned.m16n8k16.row.col.f32.f16.f16.f32 "
                        "{%0,%1,%2,%3}, {%4,%5,%6,%7}, {%8,%9}, {%0,%1,%2,%3};"
                        : "+f"(acc[mi][ni][0]), "+f"(acc[mi][ni][1]),
                          "+f"(acc[mi][ni][2]), "+f"(acc[mi][ni][3])
                        : "r"(a[mi][0]), "r"(a[mi][1]), "r"(a[mi][2]), "r"(a[mi][3]),
                          "r"(bfr[ni][0]), "r"(bfr[ni][1]));
                }
        }
        st = (st == NSTG - 1) ? 0 : st + 1;
        stp = (stp == NSTG - 1) ? 0 : stp + 1;
    }

    // epilogue: bias + sigmoid, float2 stores (n even, NNE even)
    const int rin = lane >> 2;
    const int cin = (lane & 3) * 2;
#pragma unroll
    for (int ni = 0; ni < 8; ni++) {
        int n = n0 + wn * 64 + ni * 8 + cin;
        if (n >= NNE) continue;
        float2 bz = *(const float2*)(bias + n);
#pragma unroll
        for (int mi = 0; mi < 2; mi++) {
            int m = m0 + wm * 32 + mi * 16 + rin;
            float2 o0, o1;
            o0.x = 1.f / (1.f + __expf(-(acc[mi][ni][0] + bz.x)));
            o0.y = 1.f / (1.f + __expf(-(acc[mi][ni][1] + bz.y)));
            o1.x = 1.f / (1.f + __expf(-(acc[mi][ni][2] + bz.x)));
            o1.y = 1.f / (1.f + __expf(-(acc[mi][ni][3] + bz.y)));
            *(float2*)(out + (size_t)m * NNE + n)       = o0;
            *(float2*)(out + (size_t)(m + 8) * NNE + n) = o1;
        }
    }
#undef LOAD_D
}

// ---------------------------------------------------------------------------
extern "C" void kernel_launch(void* const* d_in, const int* in_sizes, int n_in,
                              void* d_out, int out_size) {
    const int*   e1_idx = (const int*)d_in[0];
    const int*   r_idx  = (const int*)d_in[1];
    const float* E      = (const float*)d_in[2];
    const float* R      = (const float*)d_in[3];
    const float* W_fc   = (const float*)d_in[4];
    const float* b_fc   = (const float*)d_in[5];
    const float* W_fc1  = (const float*)d_in[6];
    const float* b_fc1  = (const float*)d_in[7];
    const float* bn0_g  = (const float*)d_in[8];
    const float* bn0_b  = (const float*)d_in[9];
    const float* bn0_m  = (const float*)d_in[10];
    const float* bn0_v  = (const float*)d_in[11];
    const float* bn1_g  = (const float*)d_in[12];
    const float* bn1_b  = (const float*)d_in[13];
    const float* bn1_m  = (const float*)d_in[14];
    const float* bn1_v  = (const float*)d_in[15];
    const float* bn2_g  = (const float*)d_in[16];
    const float* bn2_b  = (const float*)d_in[17];
    const float* bn2_m  = (const float*)d_in[18];
    const float* bn2_v  = (const float*)d_in[19];
    const float* bvec   = (const float*)d_in[20];
    float* out = (float*)d_out;

    static int attr_done = 0;
    if (!attr_done) {
        cudaFuncSetAttribute(kD, cudaFuncAttributeMaxDynamicSharedMemorySize, KD_SMEM);
        attr_done = 1;
    }

    convE<<<(int)(((size_t)NPAD * KP + 255) / 256), 256>>>(E);
    convW<<<(int)(((size_t)NPW * KTOT + 255) / 256), 256>>>(W_fc);
    kAB<<<B / 8, KFW>>>(e1_idx, r_idx, E, R, W_fc1, b_fc1,
                        bn0_g, bn0_b, bn0_m, bn0_v, bn1_g, bn1_b, bn1_m, bn1_v);
    kC1m<<<dim3(B / C_BM, NPW / C_BN, KSPLIT), 256>>>();
    kC2<<<(B * D + 255) / 256, 256>>>(b_fc, bn2_g, bn2_b, bn2_m, bn2_v);

    dim3 gD(B / BM, NPAD / BN);
    kD<<<gD, 256, KD_SMEM>>>(bvec, out);
}